// round 14
// baseline (speedup 1.0000x reference)
#include <cuda_runtime.h>
#include <cuda_fp16.h>
#include <stdint.h>
#include <math.h>

#define BB 8
#define NN 128
#define CC 256
#define ROWS_TOT (BB*NN)     /* 1024 */
#define CHK 64               /* K-chunk */
#define NCHK 4               /* chunks per phase */
#define THREADS 512

// ---------------- scratch ----------------
__device__ float g_q[ROWS_TOT*CC];
__device__ float g_k[ROWS_TOT*CC];      // natural layout [bm][c]
__device__ float g_v[ROWS_TOT*CC];
__device__ __align__(16) __half g_WkaT[CC*CC];   // W^T, single fp16
__device__ __align__(16) __half g_WvaT[CC*CC];
__device__ __align__(16) __half g_WoedT[CC*CC];

// ---------------- helpers ----------------
__device__ __forceinline__ void mma_f16(float acc[4],
    uint32_t a0, uint32_t a1, uint32_t a2, uint32_t a3,
    uint32_t b0, uint32_t b1)
{
    asm volatile(
        "mma.sync.aligned.m16n8k16.row.col.f32.f16.f16.f32 "
        "{%0,%1,%2,%3}, {%4,%5,%6,%7}, {%8,%9}, {%0,%1,%2,%3};"
        : "+f"(acc[0]), "+f"(acc[1]), "+f"(acc[2]), "+f"(acc[3])
        : "r"(a0), "r"(a1), "r"(a2), "r"(a3), "r"(b0), "r"(b1));
}

#define LDSM_X4(rg, addr) \
    asm volatile("ldmatrix.sync.aligned.m8n8.x4.shared.b16 {%0,%1,%2,%3}, [%4];" \
        : "=r"((rg)[0]), "=r"((rg)[1]), "=r"((rg)[2]), "=r"((rg)[3]) : "r"(addr))

// fp32 -> fp16 hi/lo split, two values packed per word (A staging)
__device__ __forceinline__ void split2h(float a, float b, uint32_t& hi, uint32_t& lo) {
    __half ha = __float2half_rn(a), hb = __float2half_rn(b);
    hi = ((uint32_t)__half_as_ushort(hb) << 16) | __half_as_ushort(ha);
    __half la = __float2half_rn(a - __half2float(ha));
    __half lb = __float2half_rn(b - __half2float(hb));
    lo = ((uint32_t)__half_as_ushort(lb) << 16) | __half_as_ushort(la);
}

// two fp32 -> one packed fp16x2 word (attn store, single precision)
__device__ __forceinline__ uint32_t pack2h(float a, float b) {
    return ((uint32_t)__half_as_ushort(__float2half_rn(b)) << 16)
         | __half_as_ushort(__float2half_rn(a));
}
__device__ __forceinline__ float exh(uint32_t u, int odd) {
    unsigned short s = odd ? (unsigned short)(u >> 16) : (unsigned short)(u & 0xffff);
    return __half2float(__ushort_as_half(s));
}

__device__ __forceinline__ uint32_t smem_to_u32(const void* p) {
    uint32_t a;
    asm("{ .reg .u64 t; cvta.to.shared.u64 t, %1; cvt.u32.u64 %0, t; }" : "=r"(a) : "l"(p));
    return a;
}

#define CP_ASYNC16(dst_u32, src_ptr) \
    asm volatile("cp.async.cg.shared.global [%0], [%1], 16;" \
        :: "r"(dst_u32), "l"(src_ptr) : "memory")
#define CP_COMMIT()  asm volatile("cp.async.commit_group;" ::: "memory")
#define CP_WAIT0()   asm volatile("cp.async.wait_group 0;" ::: "memory")

// Swizzle for 128-byte rows (64 fp16 = 32 words): word w of row r at byte
// r*128 + ((w ^ ((r&7)<<2))<<2). Round-3-verified pattern; 16B units stay
// contiguous (xor touches word bits >=2) -> ldmatrix-compatible; 8 rows map
// to 8 distinct 16B units covering all banks -> conflict-free.
__device__ __forceinline__ uint32_t swz(int row, int w) {
    return (uint32_t)(row*128 + ((w ^ ((row & 7) << 2)) << 2));
}

// ---------------- SMEM layout (bytes) ----------------
#define OFF_QS    0          /* 1K */
#define OFF_NODES 1024       /* 1K */
#define OFF_A     2048       /* 2 bufs x (hi 16K + lo 16K) = 64K; reduce scratch later */
#define ABUF_B    32768
#define OFF_B     67584      /* 2 bufs x 32K = 64K (single fp16 weights) */
#define BBUF_B    32768
#define OFF_ATH   133120     /* attn (single fp16): 4 slabs x 16K = 64K */
#define SMEM_BYTES 198656

// ---------------- prep: weight transpose (fp16) + qkv + prot_annot copy -----
__global__ __launch_bounds__(256) void prep_kernel(
    const float* __restrict__ Wka, const float* __restrict__ Wva,
    const float* __restrict__ Woed,
    const float* __restrict__ mol, const float* __restrict__ prot,
    const float* __restrict__ Wq, const float* __restrict__ bq,
    const float* __restrict__ Wk, const float* __restrict__ bk,
    const float* __restrict__ Wv, const float* __restrict__ bv,
    float* __restrict__ out_prot_annot)
{
    __shared__ float SH[8448];
    int tid = threadIdx.x;
    int bid = blockIdx.x;
    if (bid < 24) {
        int mat = bid >> 3, k0 = (bid & 7) * 32;
        const float* W = (mat == 0) ? Wka : (mat == 1) ? Wva : Woed;
        __half* G = (mat == 0) ? g_WkaT : (mat == 1) ? g_WvaT : g_WoedT;
        for (int i = tid; i < 32*256; i += 256) {
            int kk = i >> 8, n = i & 255;
            SH[kk*257 + n] = W[(k0 + kk)*CC + n];
        }
        __syncthreads();
        int n = tid;
        uint32_t w[16];
#pragma unroll
        for (int j = 0; j < 16; j++) {
            __half h0 = __float2half_rn(SH[(2*j)*257 + n]);
            __half h1 = __float2half_rn(SH[(2*j+1)*257 + n]);
            w[j] = ((uint32_t)__half_as_ushort(h1) << 16) | __half_as_ushort(h0);
        }
        uint4* d = (uint4*)(G + n*CC + k0);
#pragma unroll
        for (int j = 0; j < 4; j++)
            d[j] = make_uint4(w[j*4], w[j*4+1], w[j*4+2], w[j*4+3]);
    } else if (bid < 280) {
        // qkv: 4 rows per block, 256 blocks
        float* Am = SH;
        float* Ap = SH + 1056;
        int r0 = (bid - 24) * 4;
        for (int i = tid; i < 4*CC; i += 256) {
            int r = i >> 8, c = i & 255;
            Am[i] = mol [(r0 + r)*CC + c];
            Ap[i] = prot[(r0 + r)*CC + c];
        }
        __syncthreads();
        int c = tid;
        float aq[4], ak[4], av[4];
#pragma unroll
        for (int r = 0; r < 4; r++) { aq[r]=0.f; ak[r]=0.f; av[r]=0.f; }
        for (int k = 0; k < CC; k++) {
            float wq = Wq[k*CC + c], wk = Wk[k*CC + c], wv = Wv[k*CC + c];
#pragma unroll
            for (int r = 0; r < 4; r++) {
                float am = Am[r*CC + k], ap = Ap[r*CC + k];
                aq[r] += am*wq; ak[r] += ap*wk; av[r] += am*wv;
            }
        }
        float bqv = bq[c], bkv = bk[c], bvv = bv[c];
#pragma unroll
        for (int r = 0; r < 4; r++) {
            g_q[(r0+r)*CC + c] = aq[r] + bqv;
            g_k[(r0+r)*CC + c] = ak[r] + bkv;
            g_v[(r0+r)*CC + c] = av[r] + bvv;
        }
    } else {
        const float4* src = (const float4*)prot;
        float4* dst = (float4*)out_prot_annot;
        int base = (bid - 280) * 2048;
#pragma unroll
        for (int u = 0; u < 8; u++)
            dst[base + u*256 + tid] = src[base + u*256 + tid];
    }
}

extern __shared__ char smem_raw[];

// ---------------- staging (512 threads, K=64 chunks) ----------------
__device__ __forceinline__ void ldgA(float4 pf[4], const float* __restrict__ Ag,
                                     int k0, int tid)
{
#pragma unroll
    for (int u = 0; u < 4; u++) {
        int idx = u*THREADS + tid;
        int row = idx >> 4, j = idx & 15;
        pf[u] = *(const float4*)(Ag + row*CC + k0 + j*4);
    }
}

__device__ __forceinline__ void stsA(char* ab, const float4 pf[4], int tid,
                                     float* __restrict__ outp, int k0)
{
#pragma unroll
    for (int u = 0; u < 4; u++) {
        int idx = u*THREADS + tid;
        int row = idx >> 4, j = idx & 15;
        uint32_t h01, l01, h23, l23;
        split2h(pf[u].x, pf[u].y, h01, l01);
        split2h(pf[u].z, pf[u].w, h23, l23);
        uint32_t boff = swz(row, j*2);
        *(uint2*)(ab + boff)         = make_uint2(h01, h23);
        *(uint2*)(ab + 16384 + boff) = make_uint2(l01, l23);
        if (outp) *(float4*)(outp + row*CC + k0 + j*4) = pf[u];
    }
}

// Weight chunk: single fp16, 32KB (256 rows x 64 halves), 4 cp.async/thread.
__device__ __forceinline__ void cpB(uint32_t bb,
    const __half* __restrict__ W, int k0, int tid)
{
#pragma unroll
    for (int u = 0; u < 4; u++) {
        int idx = u*THREADS + tid;
        int row = idx >> 3, tq = idx & 7;
        CP_ASYNC16(bb + swz(row, tq*4), W + row*CC + k0 + tq*8);
    }
    CP_COMMIT();
}

// MMA over staged K=64 chunk; A fp16 hi/lo (2-term), B fp16 single.
__device__ __forceinline__ void mma_chunk(
    uint32_t ah_b, uint32_t al_b, uint32_t b_b,
    float acc[2][8][4], int R0, int C0, int lane)
{
    const int t = lane >> 3, r = lane & 7;
    const int arow = (t & 1)*8 + r, acolw = (t >> 1)*4;
    const int brow = (t >> 1)*8 + r, bcolw = (t & 1)*4;
#pragma unroll
    for (int kk = 0; kk < 4; kk++) {
        const int wA = kk*8;
        uint32_t a0h[4], a1h[4], a0l[4], a1l[4], b0[4], b1[4];
        uint32_t aoff0 = swz(R0 + arow, wA + acolw);
        uint32_t aoff1 = swz(R0 + 16 + arow, wA + acolw);
        LDSM_X4(a0h, ah_b + aoff0);
        LDSM_X4(a1h, ah_b + aoff1);
        LDSM_X4(a0l, al_b + aoff0);
        LDSM_X4(a1l, al_b + aoff1);
        LDSM_X4(b0, b_b + swz(C0 + brow, wA + bcolw));
#pragma unroll
        for (int ntp = 0; ntp < 4; ntp++) {
            uint32_t* bc = (ntp & 1) ? b1 : b0;
            uint32_t* bn = (ntp & 1) ? b0 : b1;
            if (ntp < 3) LDSM_X4(bn, b_b + swz(C0 + (ntp+1)*16 + brow, wA + bcolw));
            mma_f16(acc[0][2*ntp],   a0h[0],a0h[1],a0h[2],a0h[3], bc[0],bc[1]);
            mma_f16(acc[1][2*ntp],   a1h[0],a1h[1],a1h[2],a1h[3], bc[0],bc[1]);
            mma_f16(acc[0][2*ntp+1], a0h[0],a0h[1],a0h[2],a0h[3], bc[2],bc[3]);
            mma_f16(acc[1][2*ntp+1], a1h[0],a1h[1],a1h[2],a1h[3], bc[2],bc[3]);
            mma_f16(acc[0][2*ntp],   a0l[0],a0l[1],a0l[2],a0l[3], bc[0],bc[1]);
            mma_f16(acc[1][2*ntp],   a1l[0],a1l[1],a1l[2],a1l[3], bc[0],bc[1]);
            mma_f16(acc[0][2*ntp+1], a0l[0],a0l[1],a0l[2],a0l[3], bc[2],bc[3]);
            mma_f16(acc[1][2*ntp+1], a1l[0],a1l[1],a1l[2],a1l[3], bc[2],bc[3]);
        }
    }
}

// Phase C single-term variant: STRAIGHTLINE (round-12 verified style).
__device__ __forceinline__ void mma_chunk1(
    uint32_t ah_b, uint32_t b_b,
    float acc[2][8][4], int R0, int C0, int lane)
{
    const int t = lane >> 3, r = lane & 7;
    const int arow = (t & 1)*8 + r, acolw = (t >> 1)*4;
    const int brow = (t >> 1)*8 + r, bcolw = (t & 1)*4;
#pragma unroll
    for (int kk = 0; kk < 4; kk++) {
        const int wA = kk*8;
        uint32_t a0[4], a1[4];
        LDSM_X4(a0, ah_b + swz(R0 + arow, wA + acolw));
        LDSM_X4(a1, ah_b + swz(R0 + 16 + arow, wA + acolw));
#pragma unroll
        for (int ntp = 0; ntp < 4; ntp++) {
            uint32_t bb[4];
            LDSM_X4(bb, b_b + swz(C0 + ntp*16 + brow, wA + bcolw));
            mma_f16(acc[0][2*ntp],   a0[0],a0[1],a0[2],a0[3], bb[0],bb[1]);
            mma_f16(acc[1][2*ntp],   a1[0],a1[1],a1[2],a1[3], bb[0],bb[1]);
            mma_f16(acc[0][2*ntp+1], a0[0],a0[1],a0[2],a0[3], bb[2],bb[3]);
            mma_f16(acc[1][2*ntp+1], a1[0],a1[1],a1[2],a1[3], bb[2],bb[3]);
        }
    }
}

#define ZERO_ACC(acc) \
    _Pragma("unroll") for (int mt = 0; mt < 2; mt++) \
    _Pragma("unroll") for (int nt = 0; nt < 8; nt++) \
    _Pragma("unroll") for (int i = 0; i < 4; i++) acc[mt][nt][i] = 0.f;

// ---------------- fused edge kernel, one CTA per (b,m), 512 threads ---------
// attn stored as SINGLE fp16 in 4 k-slabs, SCALED x256.
__global__ __launch_bounds__(THREADS, 1) void edge_kernel(
    const float* __restrict__ mol_adj, const float* __restrict__ prot_adj,
    const float* __restrict__ bka,  const float* __restrict__ bva,
    const float* __restrict__ boed, const float* __restrict__ bond,
    const float* __restrict__ Wond,
    float* __restrict__ out_node, float* __restrict__ out_edge,
    float* __restrict__ out_prot_adj)
{
    char* sm = smem_raw;
    const uint32_t sbase = smem_to_u32(sm);
    const int tid = threadIdx.x, wid = tid >> 5, lane = tid & 31;
    const int lg = lane >> 2, lt = lane & 3;
    const int bm = blockIdx.x, b = bm >> 7;
    const int R0 = (wid >> 2)*32, C0 = (wid & 3)*64;   // 4x4 warp grid

    float* qs = (float*)(sm + OFF_QS);
    const float* Ap = prot_adj + (size_t)bm*NN*CC;
    const float* Am = mol_adj  + (size_t)bm*NN*CC;
    float* outp = out_prot_adj + (size_t)bm*NN*CC;

    if (tid < 256) qs[tid] = g_q[bm*CC + tid];

    float acc[2][8][4];
    float4 pf[4];

    // prologue
    ldgA(pf, Ap, 0, tid);
    cpB(sbase + OFF_B, g_WkaT, 0, tid);
    __syncthreads();

    // ======== Phase A: prot_e (writes prot passthrough from pf) ========
    ZERO_ACC(acc);
    for (int ch = 0; ch < NCHK; ch++) {
        char* ab = sm + OFF_A + (ch & 1)*ABUF_B;
        uint32_t abu = sbase + OFF_A + (ch & 1)*ABUF_B;
        stsA(ab, pf, tid, outp, ch*CHK);
        if (ch < NCHK-1) ldgA(pf, Ap, (ch+1)*CHK, tid);
        else             ldgA(pf, Am, 0, tid);
        CP_WAIT0();
        __syncthreads();
        uint32_t nb = sbase + OFF_B + (((ch & 1) ^ 1))*BBUF_B;
        if (ch < NCHK-1) cpB(nb, g_WkaT, (ch+1)*CHK, tid);
        else             cpB(nb, g_WvaT, 0, tid);
        uint32_t bbu = sbase + OFF_B + (ch & 1)*BBUF_B;
        mma_chunk(abu, abu + 16384, bbu, acc, R0, C0, lane);
    }
    // epilogue A: attn := fp16(pe + bka + 1)
#pragma unroll
    for (int mt = 0; mt < 2; mt++) {
        int r = R0 + mt*16 + lg;
#pragma unroll
        for (int nt = 0; nt < 8; nt++) {
            int c = C0 + nt*8 + lt*2;
            uint32_t coff = ((uint32_t)(c >> 6))*16384u;
            int wloc = (c & 63) >> 1;
            float b0v = __ldg(bka + c) + 1.0f, b1v = __ldg(bka + c + 1) + 1.0f;
            *(uint32_t*)(sm + OFF_ATH + coff + swz(r, wloc)) =
                pack2h(acc[mt][nt][0] + b0v, acc[mt][nt][1] + b1v);
            *(uint32_t*)(sm + OFF_ATH + coff + swz(r + 8, wloc)) =
                pack2h(acc[mt][nt][2] + b0v, acc[mt][nt][3] + b1v);
        }
    }

    // ======== Phase B: mol_e ========
    ZERO_ACC(acc);
    for (int ch = 0; ch < NCHK; ch++) {
        char* ab = sm + OFF_A + (ch & 1)*ABUF_B;
        uint32_t abu = sbase + OFF_A + (ch & 1)*ABUF_B;
        stsA(ab, pf, tid, (float*)0, 0);
        if (ch < NCHK-1) ldgA(pf, Am, (ch+1)*CHK, tid);
        CP_WAIT0();
        __syncthreads();
        uint32_t nb = sbase + OFF_B + (((ch & 1) ^ 1))*BBUF_B;
        if (ch < NCHK-1) cpB(nb, g_WvaT, (ch+1)*CHK, tid);
        else             cpB(nb, g_WoedT, 0, tid);
        uint32_t bbu = sbase + OFF_B + (ch & 1)*BBUF_B;
        mma_chunk(abu, abu + 16384, bbu, acc, R0, C0, lane);
    }
    // epilogue B: attn_scaled = pe * (me + bva) * (q*16) * k   [= true*256]
    {
        const int bbase = b << 7;
#pragma unroll
        for (int mt = 0; mt < 2; mt++) {
            int r = R0 + mt*16 + lg;
            int grow = bbase + r;
#pragma unroll
            for (int nt = 0; nt < 8; nt++) {
                int c = C0 + nt*8 + lt*2;
                uint32_t coff = ((uint32_t)(c >> 6))*16384u;
                int wloc = (c & 63) >> 1;
                uint32_t o0 = coff + swz(r, wloc), o1 = coff + swz(r + 8, wloc);
                float bv0 = __ldg(bva + c), bv1 = __ldg(bva + c + 1);
                float q0 = qs[c] * 16.0f, q1 = qs[c+1] * 16.0f;
                float2 kv0 = *(const float2*)(g_k + (size_t)grow*CC + c);
                float2 kv1 = *(const float2*)(g_k + (size_t)(grow + 8)*CC + c);
                uint32_t uh0 = *(uint32_t*)(sm + OFF_ATH + o0);
                uint32_t uh1 = *(uint32_t*)(sm + OFF_ATH + o1);
                float a0 = exh(uh0, 0) * (acc[mt][nt][0] + bv0) * q0 * kv0.x;
                float a1 = exh(uh0, 1) * (acc[mt][nt][1] + bv1) * q1 * kv0.y;
                float a2 = exh(uh1, 0) * (acc[mt][nt][2] + bv0) * q0 * kv1.x;
                float a3 = exh(uh1, 1) * (acc[mt][nt][3] + bv1) * q1 * kv1.y;
                *(uint32_t*)(sm + OFF_ATH + o0) = pack2h(a0, a1);
                *(uint32_t*)(sm + OFF_ATH + o1) = pack2h(a2, a3);
            }
        }
    }

    // ======== Phase C: edge_out = (attn @ Woed)/256 + boed ========
    ZERO_ACC(acc);
    for (int ch = 0; ch < NCHK; ch++) {
        CP_WAIT0();
        __syncthreads();
        if (ch < NCHK-1)
            cpB(sbase + OFF_B + (((ch & 1) ^ 1))*BBUF_B, g_WoedT, (ch+1)*CHK, tid);
        mma_chunk1(sbase + OFF_ATH + ch*16384,
                   sbase + OFF_B + (ch & 1)*BBUF_B, acc, R0, C0, lane);
    }
    // epilogue C: scale back 1/256 and store
#pragma unroll
    for (int mt = 0; mt < 2; mt++) {
        int r = R0 + mt*16 + lg;
#pragma unroll
        for (int nt = 0; nt < 8; nt++) {
            int c = C0 + nt*8 + lt*2;
            float b0v = __ldg(boed + c), b1v = __ldg(boed + c + 1);
            *(float2*)(out_edge + ((size_t)bm*NN + r)*CC + c) =
                make_float2(acc[mt][nt][0]*0.00390625f + b0v,
                            acc[mt][nt][1]*0.00390625f + b1v);
            *(float2*)(out_edge + ((size_t)bm*NN + r + 8)*CC + c) =
                make_float2(acc[mt][nt][2]*0.00390625f + b0v,
                            acc[mt][nt][3]*0.00390625f + b1v);
        }
    }

    // ======== softmax (2-way split over n) + node projection ========
    {
        float* red  = (float*)(sm + OFF_A);
        float* red2 = (float*)(sm + OFF_A + 2048);
        float* nodes = (float*)(sm + OFF_NODES);

        const int c = tid & 255, half = tid >> 8;
        const int odd = c & 1;
        const int wloc = (c & 63) >> 1;
        const char* bh = sm + OFF_ATH + ((uint32_t)(c >> 6))*16384u;
        const int n0 = half*64;

        float mx = -1e30f;
#pragma unroll 4
        for (int i = 0; i < 64; i++) {
            float v = exh(*(const uint32_t*)(bh + swz(n0 + i, wloc)), odd);
            mx = fmaxf(mx, v);
        }
        red[tid] = mx;
        __syncthreads();
        mx = fmaxf(red[c], red[256 + c]);

        float s = 0.f, nv = 0.f;
        const float* vb = g_v + (size_t)((b << 7) + n0)*CC + c;
#pragma unroll 4
        for (int i = 0; i < 64; i++) {
            float v = exh(*(const uint32_t*)(bh + swz(n0 + i, wloc)), odd);
            float e = __expf((v - mx) * 0.00390625f);
            s += e;
            nv += e * vb[(size_t)i*CC];
        }
        __syncthreads();
        red[tid] = s; red2[tid] = nv;
        __syncthreads();
        if (tid < 256)
            nodes[c] = (red2[c] + red2[256 + c]) / (red[c] + red[256 + c]);
        __syncthreads();

        float a2 = 0.f;
        const int k0 = half*128;
#pragma unroll 4
        for (int k = 0; k < 128; k++)
            a2 += nodes[k0 + k] * Wond[(k0 + k)*CC + c];
        red[tid] = a2;
        __syncthreads();
        if (tid < 256)
            out_node[bm*CC + c] = red[c] + red[256 + c] + __ldg(bond + c);
    }
}

// ---------------- launch ----------------
extern "C" void kernel_launch(void* const* d_in, const int* in_sizes, int n_in,
                              void* d_out, int out_size)
{
    const float* mol_annot  = (const float*)d_in[0];
    const float* prot_annot = (const float*)d_in[1];
    const float* mol_adj    = (const float*)d_in[2];
    const float* prot_adj   = (const float*)d_in[3];
    const float* Wq   = (const float*)d_in[4];   const float* bq   = (const float*)d_in[5];
    const float* Wk   = (const float*)d_in[6];   const float* bk   = (const float*)d_in[7];
    const float* Wv   = (const float*)d_in[8];   const float* bv   = (const float*)d_in[9];
    const float* Wka  = (const float*)d_in[10];  const float* bka  = (const float*)d_in[11];
    const float* Wva  = (const float*)d_in[12];  const float* bva  = (const float*)d_in[13];
    const float* Wond = (const float*)d_in[14];  const float* bond = (const float*)d_in[15];
    const float* Woed = (const float*)d_in[16];  const float* boed = (const float*)d_in[17];

    float* out = (float*)d_out;
    const size_t ANNOT = (size_t)BB*NN*CC;
    const size_t ADJ   = (size_t)BB*NN*NN*CC;
    float* out_node       = out;
    float* out_prot_annot = out + ANNOT;
    float* out_edge       = out + 2*ANNOT;
    float* out_prot_adj   = out + 2*ANNOT + ADJ;

    cudaFuncSetAttribute(edge_kernel,
                         cudaFuncAttributeMaxDynamicSharedMemorySize, SMEM_BYTES);

    prep_kernel<<<312, 256>>>(Wka, Wva, Woed,
                              mol_annot, prot_annot, Wq, bq, Wk, bk, Wv, bv,
                              out_prot_annot);

    edge_kernel<<<ROWS_TOT, THREADS, SMEM_BYTES>>>(
        mol_adj, prot_adj, bka, bva, boed, bond, Wond,
        out_node, out_edge, out_prot_adj);
}

// round 15
// speedup vs baseline: 1.2395x; 1.2395x over previous
#include <cuda_runtime.h>
#include <cuda_fp16.h>
#include <stdint.h>
#include <math.h>

#define BB 8
#define NN 128
#define CC 256
#define ROWS_TOT (BB*NN)     /* 1024 */
#define CHK 32               /* K-chunk */
#define NCHK 8               /* chunks per phase */
#define THREADS 512

// ---------------- scratch ----------------
__device__ float g_q[ROWS_TOT*CC];
__device__ float g_k[ROWS_TOT*CC];      // natural layout [bm][c]
__device__ float g_v[ROWS_TOT*CC];
__device__ __align__(16) __half g_WkaT[CC*CC];   // W^T, single fp16
__device__ __align__(16) __half g_WvaT[CC*CC];
__device__ __align__(16) __half g_WoedT[CC*CC];

// ---------------- helpers ----------------
__device__ __forceinline__ void mma_f16(float acc[4],
    uint32_t a0, uint32_t a1, uint32_t a2, uint32_t a3,
    uint32_t b0, uint32_t b1)
{
    asm volatile(
        "mma.sync.aligned.m16n8k16.row.col.f32.f16.f16.f32 "
        "{%0,%1,%2,%3}, {%4,%5,%6,%7}, {%8,%9}, {%0,%1,%2,%3};"
        : "+f"(acc[0]), "+f"(acc[1]), "+f"(acc[2]), "+f"(acc[3])
        : "r"(a0), "r"(a1), "r"(a2), "r"(a3), "r"(b0), "r"(b1));
}

#define LDSM_X4(rg, addr) \
    asm volatile("ldmatrix.sync.aligned.m8n8.x4.shared.b16 {%0,%1,%2,%3}, [%4];" \
        : "=r"((rg)[0]), "=r"((rg)[1]), "=r"((rg)[2]), "=r"((rg)[3]) : "r"(addr))

// two fp32 -> one packed fp16x2 word
__device__ __forceinline__ uint32_t pack2h(float a, float b) {
    return ((uint32_t)__half_as_ushort(__float2half_rn(b)) << 16)
         | __half_as_ushort(__float2half_rn(a));
}
__device__ __forceinline__ float exh(uint32_t u, int odd) {
    unsigned short s = odd ? (unsigned short)(u >> 16) : (unsigned short)(u & 0xffff);
    return __half2float(__ushort_as_half(s));
}

__device__ __forceinline__ uint32_t smem_to_u32(const void* p) {
    uint32_t a;
    asm("{ .reg .u64 t; cvta.to.shared.u64 t, %1; cvt.u32.u64 %0, t; }" : "=r"(a) : "l"(p));
    return a;
}

#define CP_ASYNC16(dst_u32, src_ptr) \
    asm volatile("cp.async.cg.shared.global [%0], [%1], 16;" \
        :: "r"(dst_u32), "l"(src_ptr) : "memory")
#define CP_COMMIT()  asm volatile("cp.async.commit_group;" ::: "memory")
#define CP_WAIT0()   asm volatile("cp.async.wait_group 0;" ::: "memory")

// Swizzle for 64-byte rows (32 fp16 = 16 words); 16B blocks stay contiguous.
__device__ __forceinline__ uint32_t swz(int row, int w) {
    return (uint32_t)(row*64 + ((w ^ (((row >> 1) & 3) << 2)) << 2));
}

// ---------------- SMEM layout (bytes) ----------------
#define OFF_QS    0          /* 1K */
#define OFF_NODES 1024       /* 1K */
#define OFF_A     2048       /* 2 bufs x 8K (single fp16 A); reduce scratch later */
#define ABUF_B    8192
#define OFF_B     18432      /* 2 bufs x 16K (single fp16 weights) */
#define BBUF_B    16384
#define OFF_ATH   51200      /* attn (single fp16): 8 chunks x 8K = 64K */
#define SMEM_BYTES 116736

// ---------------- prep: weight transpose (fp16) + qkv + prot_annot copy -----
__global__ __launch_bounds__(256) void prep_kernel(
    const float* __restrict__ Wka, const float* __restrict__ Wva,
    const float* __restrict__ Woed,
    const float* __restrict__ mol, const float* __restrict__ prot,
    const float* __restrict__ Wq, const float* __restrict__ bq,
    const float* __restrict__ Wk, const float* __restrict__ bk,
    const float* __restrict__ Wv, const float* __restrict__ bv,
    float* __restrict__ out_prot_annot)
{
    __shared__ float SH[8448];
    int tid = threadIdx.x;
    int bid = blockIdx.x;
    if (bid < 24) {
        int mat = bid >> 3, k0 = (bid & 7) * CHK;
        const float* W = (mat == 0) ? Wka : (mat == 1) ? Wva : Woed;
        __half* G = (mat == 0) ? g_WkaT : (mat == 1) ? g_WvaT : g_WoedT;
        for (int i = tid; i < 32*256; i += 256) {
            int kk = i >> 8, n = i & 255;
            SH[kk*257 + n] = W[(k0 + kk)*CC + n];
        }
        __syncthreads();
        int n = tid;
        uint32_t w[16];
#pragma unroll
        for (int j = 0; j < 16; j++) {
            __half h0 = __float2half_rn(SH[(2*j)*257 + n]);
            __half h1 = __float2half_rn(SH[(2*j+1)*257 + n]);
            w[j] = ((uint32_t)__half_as_ushort(h1) << 16) | __half_as_ushort(h0);
        }
        uint4* d = (uint4*)(G + n*CC + k0);
#pragma unroll
        for (int j = 0; j < 4; j++)
            d[j] = make_uint4(w[j*4], w[j*4+1], w[j*4+2], w[j*4+3]);
    } else if (bid < 280) {
        // qkv: 4 rows per block, 256 blocks
        float* Am = SH;
        float* Ap = SH + 1056;
        int r0 = (bid - 24) * 4;
        for (int i = tid; i < 4*CC; i += 256) {
            int r = i >> 8, c = i & 255;
            Am[i] = mol [(r0 + r)*CC + c];
            Ap[i] = prot[(r0 + r)*CC + c];
        }
        __syncthreads();
        int c = tid;
        float aq[4], ak[4], av[4];
#pragma unroll
        for (int r = 0; r < 4; r++) { aq[r]=0.f; ak[r]=0.f; av[r]=0.f; }
        for (int k = 0; k < CC; k++) {
            float wq = Wq[k*CC + c], wk = Wk[k*CC + c], wv = Wv[k*CC + c];
#pragma unroll
            for (int r = 0; r < 4; r++) {
                float am = Am[r*CC + k], ap = Ap[r*CC + k];
                aq[r] += am*wq; ak[r] += ap*wk; av[r] += am*wv;
            }
        }
        float bqv = bq[c], bkv = bk[c], bvv = bv[c];
#pragma unroll
        for (int r = 0; r < 4; r++) {
            g_q[(r0+r)*CC + c] = aq[r] + bqv;
            g_k[(r0+r)*CC + c] = ak[r] + bkv;
            g_v[(r0+r)*CC + c] = av[r] + bvv;
        }
    } else {
        const float4* src = (const float4*)prot;
        float4* dst = (float4*)out_prot_annot;
        int base = (bid - 280) * 2048;
#pragma unroll
        for (int u = 0; u < 8; u++)
            dst[base + u*256 + tid] = src[base + u*256 + tid];
    }
}

extern __shared__ char smem_raw[];

// ---------------- staging (512 threads) ----------------
__device__ __forceinline__ void ldgA(float4 pf[2], const float* __restrict__ Ag,
                                     int k0, int tid)
{
#pragma unroll
    for (int u = 0; u < 2; u++) {
        int idx = u*THREADS + tid;
        int row = idx >> 3, j = idx & 7;
        pf[u] = *(const float4*)(Ag + row*CC + k0 + j*4);
    }
}

// single-fp16 A staging (no lo term)
__device__ __forceinline__ void stsA(char* ab, const float4 pf[2], int tid,
                                     float* __restrict__ outp, int k0)
{
#pragma unroll
    for (int u = 0; u < 2; u++) {
        int idx = u*THREADS + tid;
        int row = idx >> 3, j = idx & 7;
        uint32_t h01 = pack2h(pf[u].x, pf[u].y);
        uint32_t h23 = pack2h(pf[u].z, pf[u].w);
        *(uint2*)(ab + swz(row, j*2)) = make_uint2(h01, h23);
        if (outp) *(float4*)(outp + row*CC + k0 + j*4) = pf[u];
    }
}

// Weight chunk: single fp16, 16KB, 2 cp.async per thread.
__device__ __forceinline__ void cpB(uint32_t bb,
    const __half* __restrict__ W, int k0, int tid)
{
#pragma unroll
    for (int u = 0; u < 2; u++) {
        int idx = u*THREADS + tid;
        int row = idx >> 2, t = idx & 3;
        CP_ASYNC16(bb + swz(row, t*4), W + row*CC + k0 + t*8);
    }
    CP_COMMIT();
}

// Single-term MMA over staged K=32 chunk (STRAIGHTLINE, round-12 verified).
// A fp16 single, B fp16 single. Warp tile 32x64 at (R0, C0); acc[2][8][4].
__device__ __forceinline__ void mma_chunk1(
    uint32_t ah_b, uint32_t b_b,
    float acc[2][8][4], int R0, int C0, int lane)
{
    const int t = lane >> 3, r = lane & 7;
    const int arow = (t & 1)*8 + r, acolw = (t >> 1)*4;
    const int brow = (t >> 1)*8 + r, bcolw = (t & 1)*4;
#pragma unroll
    for (int kk = 0; kk < 2; kk++) {
        const int wA = kk*8;
        uint32_t a0[4], a1[4];
        LDSM_X4(a0, ah_b + swz(R0 + arow, wA + acolw));
        LDSM_X4(a1, ah_b + swz(R0 + 16 + arow, wA + acolw));
#pragma unroll
        for (int ntp = 0; ntp < 4; ntp++) {
            uint32_t bb[4];
            LDSM_X4(bb, b_b + swz(C0 + ntp*16 + brow, wA + bcolw));
            mma_f16(acc[0][2*ntp],   a0[0],a0[1],a0[2],a0[3], bb[0],bb[1]);
            mma_f16(acc[1][2*ntp],   a1[0],a1[1],a1[2],a1[3], bb[0],bb[1]);
            mma_f16(acc[0][2*ntp+1], a0[0],a0[1],a0[2],a0[3], bb[2],bb[3]);
            mma_f16(acc[1][2*ntp+1], a1[0],a1[1],a1[2],a1[3], bb[2],bb[3]);
        }
    }
}

#define ZERO_ACC(acc) \
    _Pragma("unroll") for (int mt = 0; mt < 2; mt++) \
    _Pragma("unroll") for (int nt = 0; nt < 8; nt++) \
    _Pragma("unroll") for (int i = 0; i < 4; i++) acc[mt][nt][i] = 0.f;

// ---------------- fused edge kernel, one CTA per (b,m), 512 threads ---------
// attn stored as SINGLE fp16, SCALED x256 (q*16 in epi-B; /256 in softmax, epi-C).
__global__ __launch_bounds__(THREADS, 1) void edge_kernel(
    const float* __restrict__ mol_adj, const float* __restrict__ prot_adj,
    const float* __restrict__ bka,  const float* __restrict__ bva,
    const float* __restrict__ boed, const float* __restrict__ bond,
    const float* __restrict__ Wond,
    float* __restrict__ out_node, float* __restrict__ out_edge,
    float* __restrict__ out_prot_adj)
{
    char* sm = smem_raw;
    const uint32_t sbase = smem_to_u32(sm);
    const int tid = threadIdx.x, wid = tid >> 5, lane = tid & 31;
    const int lg = lane >> 2, lt = lane & 3;
    const int bm = blockIdx.x, b = bm >> 7;
    const int R0 = (wid >> 2)*32, C0 = (wid & 3)*64;   // 4x4 warp grid

    float* qs = (float*)(sm + OFF_QS);
    const float* Ap = prot_adj + (size_t)bm*NN*CC;
    const float* Am = mol_adj  + (size_t)bm*NN*CC;
    float* outp = out_prot_adj + (size_t)bm*NN*CC;

    if (tid < 256) qs[tid] = g_q[bm*CC + tid];

    float acc[2][8][4];
    float4 pf[2];

    // prologue
    ldgA(pf, Ap, 0, tid);
    cpB(sbase + OFF_B, g_WkaT, 0, tid);
    __syncthreads();

    // ======== Phase A: prot_e (writes prot passthrough from pf) ========
    ZERO_ACC(acc);
    for (int ch = 0; ch < NCHK; ch++) {
        char* ab = sm + OFF_A + (ch & 1)*ABUF_B;
        uint32_t abu = sbase + OFF_A + (ch & 1)*ABUF_B;
        stsA(ab, pf, tid, outp, ch*CHK);
        if (ch < 7) ldgA(pf, Ap, (ch+1)*CHK, tid);
        else        ldgA(pf, Am, 0, tid);
        CP_WAIT0();
        __syncthreads();
        uint32_t nb = sbase + OFF_B + (((ch & 1) ^ 1))*BBUF_B;
        if (ch < 7) cpB(nb, g_WkaT, (ch+1)*CHK, tid);
        else        cpB(nb, g_WvaT, 0, tid);
        uint32_t bbu = sbase + OFF_B + (ch & 1)*BBUF_B;
        mma_chunk1(abu, bbu, acc, R0, C0, lane);
    }
    // epilogue A: attn := fp16(pe + bka + 1)
#pragma unroll
    for (int mt = 0; mt < 2; mt++) {
        int r = R0 + mt*16 + lg;
#pragma unroll
        for (int nt = 0; nt < 8; nt++) {
            int c = C0 + nt*8 + lt*2;
            uint32_t coff = ((uint32_t)(c >> 5))*8192u;
            int wloc = (c & 31) >> 1;
            float b0v = __ldg(bka + c) + 1.0f, b1v = __ldg(bka + c + 1) + 1.0f;
            *(uint32_t*)(sm + OFF_ATH + coff + swz(r, wloc)) =
                pack2h(acc[mt][nt][0] + b0v, acc[mt][nt][1] + b1v);
            *(uint32_t*)(sm + OFF_ATH + coff + swz(r + 8, wloc)) =
                pack2h(acc[mt][nt][2] + b0v, acc[mt][nt][3] + b1v);
        }
    }

    // ======== Phase B: mol_e ========
    ZERO_ACC(acc);
    for (int ch = 0; ch < NCHK; ch++) {
        char* ab = sm + OFF_A + (ch & 1)*ABUF_B;
        uint32_t abu = sbase + OFF_A + (ch & 1)*ABUF_B;
        stsA(ab, pf, tid, (float*)0, 0);
        if (ch < 7) ldgA(pf, Am, (ch+1)*CHK, tid);
        CP_WAIT0();
        __syncthreads();
        uint32_t nb = sbase + OFF_B + (((ch & 1) ^ 1))*BBUF_B;
        if (ch < 7) cpB(nb, g_WvaT, (ch+1)*CHK, tid);
        else        cpB(nb, g_WoedT, 0, tid);
        uint32_t bbu = sbase + OFF_B + (ch & 1)*BBUF_B;
        mma_chunk1(abu, bbu, acc, R0, C0, lane);
    }
    // epilogue B: attn_scaled = pe * (me + bva) * (q*16) * k   [= true*256]
    {
        const int bbase = b << 7;
#pragma unroll
        for (int mt = 0; mt < 2; mt++) {
            int r = R0 + mt*16 + lg;
            int grow = bbase + r;
#pragma unroll
            for (int nt = 0; nt < 8; nt++) {
                int c = C0 + nt*8 + lt*2;
                uint32_t coff = ((uint32_t)(c >> 5))*8192u;
                int wloc = (c & 31) >> 1;
                uint32_t o0 = coff + swz(r, wloc), o1 = coff + swz(r + 8, wloc);
                float bv0 = __ldg(bva + c), bv1 = __ldg(bva + c + 1);
                float q0 = qs[c] * 16.0f, q1 = qs[c+1] * 16.0f;
                float2 kv0 = *(const float2*)(g_k + (size_t)grow*CC + c);
                float2 kv1 = *(const float2*)(g_k + (size_t)(grow + 8)*CC + c);
                uint32_t uh0 = *(uint32_t*)(sm + OFF_ATH + o0);
                uint32_t uh1 = *(uint32_t*)(sm + OFF_ATH + o1);
                float a0 = exh(uh0, 0) * (acc[mt][nt][0] + bv0) * q0 * kv0.x;
                float a1 = exh(uh0, 1) * (acc[mt][nt][1] + bv1) * q1 * kv0.y;
                float a2 = exh(uh1, 0) * (acc[mt][nt][2] + bv0) * q0 * kv1.x;
                float a3 = exh(uh1, 1) * (acc[mt][nt][3] + bv1) * q1 * kv1.y;
                *(uint32_t*)(sm + OFF_ATH + o0) = pack2h(a0, a1);
                *(uint32_t*)(sm + OFF_ATH + o1) = pack2h(a2, a3);
            }
        }
    }

    // ======== Phase C: edge_out = (attn @ Woed)/256 + boed ========
    ZERO_ACC(acc);
    for (int ch = 0; ch < NCHK; ch++) {
        CP_WAIT0();
        __syncthreads();
        if (ch < 7) cpB(sbase + OFF_B + (((ch & 1) ^ 1))*BBUF_B, g_WoedT, (ch+1)*CHK, tid);
        mma_chunk1(sbase + OFF_ATH + ch*8192,
                   sbase + OFF_B + (ch & 1)*BBUF_B, acc, R0, C0, lane);
    }
    // epilogue C: scale back 1/256 and store
#pragma unroll
    for (int mt = 0; mt < 2; mt++) {
        int r = R0 + mt*16 + lg;
#pragma unroll
        for (int nt = 0; nt < 8; nt++) {
            int c = C0 + nt*8 + lt*2;
            float b0v = __ldg(boed + c), b1v = __ldg(boed + c + 1);
            *(float2*)(out_edge + ((size_t)bm*NN + r)*CC + c) =
                make_float2(acc[mt][nt][0]*0.00390625f + b0v,
                            acc[mt][nt][1]*0.00390625f + b1v);
            *(float2*)(out_edge + ((size_t)bm*NN + r + 8)*CC + c) =
                make_float2(acc[mt][nt][2]*0.00390625f + b0v,
                            acc[mt][nt][3]*0.00390625f + b1v);
        }
    }

    // ======== softmax (2-way split over n) + node projection ========
    {
        float* red  = (float*)(sm + OFF_A);
        float* red2 = (float*)(sm + OFF_A + 2048);
        float* nodes = (float*)(sm + OFF_NODES);

        const int c = tid & 255, half = tid >> 8;
        const int odd = c & 1;
        const int wloc = (c & 31) >> 1;
        const char* bh = sm + OFF_ATH + ((uint32_t)(c >> 5))*8192u;
        const int n0 = half*64;

        float mx = -1e30f;
#pragma unroll 4
        for (int i = 0; i < 64; i++) {
            float v = exh(*(const uint32_t*)(bh + swz(n0 + i, wloc)), odd);
            mx = fmaxf(mx, v);
        }
        red[tid] = mx;
        __syncthreads();
        mx = fmaxf(red[c], red[256 + c]);

        float s = 0.f, nv = 0.f;
        const float* vb = g_v + (size_t)((b << 7) + n0)*CC + c;
#pragma unroll 4
        for (int i = 0; i < 64; i++) {
            float v = exh(*(const uint32_t*)(bh + swz(n0 + i, wloc)), odd);
            float e = __expf((v - mx) * 0.00390625f);
            s += e;
            nv += e * vb[(size_t)i*CC];
        }
        __syncthreads();
        red[tid] = s; red2[tid] = nv;
        __syncthreads();
        if (tid < 256)
            nodes[c] = (red2[c] + red2[256 + c]) / (red[c] + red[256 + c]);
        __syncthreads();

        float a2 = 0.f;
        const int k0 = half*128;
#pragma unroll 4
        for (int k = 0; k < 128; k++)
            a2 += nodes[k0 + k] * Wond[(k0 + k)*CC + c];
        red[tid] = a2;
        __syncthreads();
        if (tid < 256)
            out_node[bm*CC + c] = red[c] + red[256 + c] + __ldg(bond + c);
    }
}

// ---------------- launch ----------------
extern "C" void kernel_launch(void* const* d_in, const int* in_sizes, int n_in,
                              void* d_out, int out_size)
{
    const float* mol_annot  = (const float*)d_in[0];
    const float* prot_annot = (const float*)d_in[1];
    const float* mol_adj    = (const float*)d_in[2];
    const float* prot_adj   = (const float*)d_in[3];
    const float* Wq   = (const float*)d_in[4];   const float* bq   = (const float*)d_in[5];
    const float* Wk   = (const float*)d_in[6];   const float* bk   = (const float*)d_in[7];
    const float* Wv   = (const float*)d_in[8];   const float* bv   = (const float*)d_in[9];
    const float* Wka  = (const float*)d_in[10];  const float* bka  = (const float*)d_in[11];
    const float* Wva  = (const float*)d_in[12];  const float* bva  = (const float*)d_in[13];
    const float* Wond = (const float*)d_in[14];  const float* bond = (const float*)d_in[15];
    const float* Woed = (const float*)d_in[16];  const float* boed = (const float*)d_in[17];

    float* out = (float*)d_out;
    const size_t ANNOT = (size_t)BB*NN*CC;
    const size_t ADJ   = (size_t)BB*NN*NN*CC;
    float* out_node       = out;
    float* out_prot_annot = out + ANNOT;
    float* out_edge       = out + 2*ANNOT;
    float* out_prot_adj   = out + 2*ANNOT + ADJ;

    cudaFuncSetAttribute(edge_kernel,
                         cudaFuncAttributeMaxDynamicSharedMemorySize, SMEM_BYTES);

    prep_kernel<<<312, 256>>>(Wka, Wva, Woed,
                              mol_annot, prot_annot, Wq, bq, Wk, bk, Wv, bv,
                              out_prot_annot);

    edge_kernel<<<ROWS_TOT, THREADS, SMEM_BYTES>>>(
        mol_adj, prot_adj, bka, bva, boed, bond, Wond,
        out_node, out_edge, out_prot_adj);
}

// round 16
// speedup vs baseline: 1.4003x; 1.1297x over previous
#include <cuda_runtime.h>
#include <cuda_fp16.h>
#include <stdint.h>
#include <math.h>

#define BB 8
#define NN 128
#define CC 256
#define ROWS_TOT (BB*NN)     /* 1024 */
#define CHK 32               /* K-chunk */
#define NCHK 8               /* chunks per phase */
#define THREADS 512

// ---------------- scratch ----------------
__device__ float g_q[ROWS_TOT*CC];
__device__ float g_k[ROWS_TOT*CC];      // natural layout [bm][c]
__device__ float g_v[ROWS_TOT*CC];
__device__ __align__(16) __half g_WkaT[CC*CC];   // W^T, single fp16
__device__ __align__(16) __half g_WvaT[CC*CC];
__device__ __align__(16) __half g_WoedT[CC*CC];

// ---------------- helpers ----------------
__device__ __forceinline__ void mma_f16(float acc[4],
    uint32_t a0, uint32_t a1, uint32_t a2, uint32_t a3,
    uint32_t b0, uint32_t b1)
{
    asm volatile(
        "mma.sync.aligned.m16n8k16.row.col.f32.f16.f16.f32 "
        "{%0,%1,%2,%3}, {%4,%5,%6,%7}, {%8,%9}, {%0,%1,%2,%3};"
        : "+f"(acc[0]), "+f"(acc[1]), "+f"(acc[2]), "+f"(acc[3])
        : "r"(a0), "r"(a1), "r"(a2), "r"(a3), "r"(b0), "r"(b1));
}

#define LDSM_X4(rg, addr) \
    asm volatile("ldmatrix.sync.aligned.m8n8.x4.shared.b16 {%0,%1,%2,%3}, [%4];" \
        : "=r"((rg)[0]), "=r"((rg)[1]), "=r"((rg)[2]), "=r"((rg)[3]) : "r"(addr))

// two fp32 -> one packed fp16x2 word
__device__ __forceinline__ uint32_t pack2h(float a, float b) {
    return ((uint32_t)__half_as_ushort(__float2half_rn(b)) << 16)
         | __half_as_ushort(__float2half_rn(a));
}
__device__ __forceinline__ float exh(uint32_t u, int odd) {
    unsigned short s = odd ? (unsigned short)(u >> 16) : (unsigned short)(u & 0xffff);
    return __half2float(__ushort_as_half(s));
}

__device__ __forceinline__ uint32_t smem_to_u32(const void* p) {
    uint32_t a;
    asm("{ .reg .u64 t; cvta.to.shared.u64 t, %1; cvt.u32.u64 %0, t; }" : "=r"(a) : "l"(p));
    return a;
}

#define CP_ASYNC16(dst_u32, src_ptr) \
    asm volatile("cp.async.cg.shared.global [%0], [%1], 16;" \
        :: "r"(dst_u32), "l"(src_ptr) : "memory")
#define CP_COMMIT()  asm volatile("cp.async.commit_group;" ::: "memory")
#define CP_WAIT0()   asm volatile("cp.async.wait_group 0;" ::: "memory")

// Swizzle for 64-byte rows (32 fp16 = 16 words); 16B blocks stay contiguous.
__device__ __forceinline__ uint32_t swz(int row, int w) {
    return (uint32_t)(row*64 + ((w ^ (((row >> 1) & 3) << 2)) << 2));
}

// ---------------- SMEM layout (bytes) ----------------
#define OFF_QS    0          /* 1K */
#define OFF_NODES 1024       /* 1K */
#define OFF_A     2048       /* 2 bufs x 8K (single fp16 A); reduce scratch later */
#define ABUF_B    8192
#define OFF_B     18432      /* 2 bufs x 16K (single fp16 weights) */
#define BBUF_B    16384
#define OFF_ATH   51200      /* attn (single fp16): 8 chunks x 8K = 64K */
#define SMEM_BYTES 116736

// ---------------- prep: weight transpose (fp16) + qkv + prot_annot copy -----
__global__ __launch_bounds__(256) void prep_kernel(
    const float* __restrict__ Wka, const float* __restrict__ Wva,
    const float* __restrict__ Woed,
    const float* __restrict__ mol, const float* __restrict__ prot,
    const float* __restrict__ Wq, const float* __restrict__ bq,
    const float* __restrict__ Wk, const float* __restrict__ bk,
    const float* __restrict__ Wv, const float* __restrict__ bv,
    float* __restrict__ out_prot_annot)
{
    __shared__ float SH[8448];
    int tid = threadIdx.x;
    int bid = blockIdx.x;
    if (bid < 24) {
        int mat = bid >> 3, k0 = (bid & 7) * CHK;
        const float* W = (mat == 0) ? Wka : (mat == 1) ? Wva : Woed;
        __half* G = (mat == 0) ? g_WkaT : (mat == 1) ? g_WvaT : g_WoedT;
        for (int i = tid; i < 32*256; i += 256) {
            int kk = i >> 8, n = i & 255;
            SH[kk*257 + n] = W[(k0 + kk)*CC + n];
        }
        __syncthreads();
        int n = tid;
        uint32_t w[16];
#pragma unroll
        for (int j = 0; j < 16; j++) {
            __half h0 = __float2half_rn(SH[(2*j)*257 + n]);
            __half h1 = __float2half_rn(SH[(2*j+1)*257 + n]);
            w[j] = ((uint32_t)__half_as_ushort(h1) << 16) | __half_as_ushort(h0);
        }
        uint4* d = (uint4*)(G + n*CC + k0);
#pragma unroll
        for (int j = 0; j < 4; j++)
            d[j] = make_uint4(w[j*4], w[j*4+1], w[j*4+2], w[j*4+3]);
    } else if (bid < 280) {
        // qkv: 4 rows per block, 256 blocks
        float* Am = SH;
        float* Ap = SH + 1056;
        int r0 = (bid - 24) * 4;
        for (int i = tid; i < 4*CC; i += 256) {
            int r = i >> 8, c = i & 255;
            Am[i] = mol [(r0 + r)*CC + c];
            Ap[i] = prot[(r0 + r)*CC + c];
        }
        __syncthreads();
        int c = tid;
        float aq[4], ak[4], av[4];
#pragma unroll
        for (int r = 0; r < 4; r++) { aq[r]=0.f; ak[r]=0.f; av[r]=0.f; }
        for (int k = 0; k < CC; k++) {
            float wq = Wq[k*CC + c], wk = Wk[k*CC + c], wv = Wv[k*CC + c];
#pragma unroll
            for (int r = 0; r < 4; r++) {
                float am = Am[r*CC + k], ap = Ap[r*CC + k];
                aq[r] += am*wq; ak[r] += ap*wk; av[r] += am*wv;
            }
        }
        float bqv = bq[c], bkv = bk[c], bvv = bv[c];
#pragma unroll
        for (int r = 0; r < 4; r++) {
            g_q[(r0+r)*CC + c] = aq[r] + bqv;
            g_k[(r0+r)*CC + c] = ak[r] + bkv;
            g_v[(r0+r)*CC + c] = av[r] + bvv;
        }
    } else {
        const float4* src = (const float4*)prot;
        float4* dst = (float4*)out_prot_annot;
        int base = (bid - 280) * 2048;
#pragma unroll
        for (int u = 0; u < 8; u++)
            dst[base + u*256 + tid] = src[base + u*256 + tid];
    }
}

extern __shared__ char smem_raw[];

// ---------------- staging (512 threads) ----------------
__device__ __forceinline__ void ldgA(float4 pf[2], const float* __restrict__ Ag,
                                     int k0, int tid)
{
#pragma unroll
    for (int u = 0; u < 2; u++) {
        int idx = u*THREADS + tid;
        int row = idx >> 3, j = idx & 7;
        pf[u] = *(const float4*)(Ag + row*CC + k0 + j*4);
    }
}

// single-fp16 A staging (no lo term)
__device__ __forceinline__ void stsA(char* ab, const float4 pf[2], int tid,
                                     float* __restrict__ outp, int k0)
{
#pragma unroll
    for (int u = 0; u < 2; u++) {
        int idx = u*THREADS + tid;
        int row = idx >> 3, j = idx & 7;
        uint32_t h01 = pack2h(pf[u].x, pf[u].y);
        uint32_t h23 = pack2h(pf[u].z, pf[u].w);
        *(uint2*)(ab + swz(row, j*2)) = make_uint2(h01, h23);
        if (outp) *(float4*)(outp + row*CC + k0 + j*4) = pf[u];
    }
}

// Weight chunk: single fp16, 16KB, 2 cp.async per thread.
__device__ __forceinline__ void cpB(uint32_t bb,
    const __half* __restrict__ W, int k0, int tid)
{
#pragma unroll
    for (int u = 0; u < 2; u++) {
        int idx = u*THREADS + tid;
        int row = idx >> 2, t = idx & 3;
        CP_ASYNC16(bb + swz(row, t*4), W + row*CC + k0 + t*8);
    }
    CP_COMMIT();
}

// Single-term MMA over staged K=32 chunk (STRAIGHTLINE, round-12 verified).
// A fp16 single, B fp16 single. Warp tile 32x64 at (R0, C0); acc[2][8][4].
__device__ __forceinline__ void mma_chunk1(
    uint32_t ah_b, uint32_t b_b,
    float acc[2][8][4], int R0, int C0, int lane)
{
    const int t = lane >> 3, r = lane & 7;
    const int arow = (t & 1)*8 + r, acolw = (t >> 1)*4;
    const int brow = (t >> 1)*8 + r, bcolw = (t & 1)*4;
#pragma unroll
    for (int kk = 0; kk < 2; kk++) {
        const int wA = kk*8;
        uint32_t a0[4], a1[4];
        LDSM_X4(a0, ah_b + swz(R0 + arow, wA + acolw));
        LDSM_X4(a1, ah_b + swz(R0 + 16 + arow, wA + acolw));
#pragma unroll
        for (int ntp = 0; ntp < 4; ntp++) {
            uint32_t bb[4];
            LDSM_X4(bb, b_b + swz(C0 + ntp*16 + brow, wA + bcolw));
            mma_f16(acc[0][2*ntp],   a0[0],a0[1],a0[2],a0[3], bb[0],bb[1]);
            mma_f16(acc[1][2*ntp],   a1[0],a1[1],a1[2],a1[3], bb[0],bb[1]);
            mma_f16(acc[0][2*ntp+1], a0[0],a0[1],a0[2],a0[3], bb[2],bb[3]);
            mma_f16(acc[1][2*ntp+1], a1[0],a1[1],a1[2],a1[3], bb[2],bb[3]);
        }
    }
}

#define ZERO_ACC(acc) \
    _Pragma("unroll") for (int mt = 0; mt < 2; mt++) \
    _Pragma("unroll") for (int nt = 0; nt < 8; nt++) \
    _Pragma("unroll") for (int i = 0; i < 4; i++) acc[mt][nt][i] = 0.f;

// ---------------- fused edge kernel, one CTA per (b,m), 512 threads ---------
// attn stored as SINGLE fp16, SCALED x256 (q*16 in epi-B; /256 in softmax, epi-C).
__global__ __launch_bounds__(THREADS, 1) void edge_kernel(
    const float* __restrict__ mol_adj, const float* __restrict__ prot_adj,
    const float* __restrict__ bka,  const float* __restrict__ bva,
    const float* __restrict__ boed, const float* __restrict__ bond,
    const float* __restrict__ Wond,
    float* __restrict__ out_node, float* __restrict__ out_edge,
    float* __restrict__ out_prot_adj)
{
    char* sm = smem_raw;
    const uint32_t sbase = smem_to_u32(sm);
    const int tid = threadIdx.x, wid = tid >> 5, lane = tid & 31;
    const int lg = lane >> 2, lt = lane & 3;
    const int bm = blockIdx.x, b = bm >> 7;
    const int R0 = (wid >> 2)*32, C0 = (wid & 3)*64;   // 4x4 warp grid

    float* qs = (float*)(sm + OFF_QS);
    const float* Ap = prot_adj + (size_t)bm*NN*CC;
    const float* Am = mol_adj  + (size_t)bm*NN*CC;
    float* outp = out_prot_adj + (size_t)bm*NN*CC;

    if (tid < 256) qs[tid] = g_q[bm*CC + tid];

    float acc[2][8][4];
    float4 pf[2];

    // prologue
    ldgA(pf, Ap, 0, tid);
    cpB(sbase + OFF_B, g_WkaT, 0, tid);
    __syncthreads();

    // ======== Phase A: prot_e (writes prot passthrough from pf) ========
    ZERO_ACC(acc);
    for (int ch = 0; ch < NCHK; ch++) {
        char* ab = sm + OFF_A + (ch & 1)*ABUF_B;
        uint32_t abu = sbase + OFF_A + (ch & 1)*ABUF_B;
        stsA(ab, pf, tid, outp, ch*CHK);
        if (ch < 7) ldgA(pf, Ap, (ch+1)*CHK, tid);
        else        ldgA(pf, Am, 0, tid);
        CP_WAIT0();
        __syncthreads();
        uint32_t nb = sbase + OFF_B + (((ch & 1) ^ 1))*BBUF_B;
        if (ch < 7) cpB(nb, g_WkaT, (ch+1)*CHK, tid);
        else        cpB(nb, g_WvaT, 0, tid);
        uint32_t bbu = sbase + OFF_B + (ch & 1)*BBUF_B;
        mma_chunk1(abu, bbu, acc, R0, C0, lane);
    }
    // epilogue A: attn := fp16(pe + bka + 1)
#pragma unroll
    for (int mt = 0; mt < 2; mt++) {
        int r = R0 + mt*16 + lg;
#pragma unroll
        for (int nt = 0; nt < 8; nt++) {
            int c = C0 + nt*8 + lt*2;
            uint32_t coff = ((uint32_t)(c >> 5))*8192u;
            int wloc = (c & 31) >> 1;
            float b0v = __ldg(bka + c) + 1.0f, b1v = __ldg(bka + c + 1) + 1.0f;
            *(uint32_t*)(sm + OFF_ATH + coff + swz(r, wloc)) =
                pack2h(acc[mt][nt][0] + b0v, acc[mt][nt][1] + b1v);
            *(uint32_t*)(sm + OFF_ATH + coff + swz(r + 8, wloc)) =
                pack2h(acc[mt][nt][2] + b0v, acc[mt][nt][3] + b1v);
        }
    }

    // ======== Phase B: mol_e ========
    ZERO_ACC(acc);
    for (int ch = 0; ch < NCHK; ch++) {
        char* ab = sm + OFF_A + (ch & 1)*ABUF_B;
        uint32_t abu = sbase + OFF_A + (ch & 1)*ABUF_B;
        stsA(ab, pf, tid, (float*)0, 0);
        if (ch < 7) ldgA(pf, Am, (ch+1)*CHK, tid);
        CP_WAIT0();
        __syncthreads();
        uint32_t nb = sbase + OFF_B + (((ch & 1) ^ 1))*BBUF_B;
        if (ch < 7) cpB(nb, g_WvaT, (ch+1)*CHK, tid);
        else        cpB(nb, g_WoedT, 0, tid);
        uint32_t bbu = sbase + OFF_B + (ch & 1)*BBUF_B;
        mma_chunk1(abu, bbu, acc, R0, C0, lane);
    }
    // epilogue B: attn_scaled = pe * (me + bva) * (q*16) * k   [= true*256]
    // g_k loads hoisted per mt-group into registers (MLP 2 -> 16)
    {
        const int bbase = b << 7;
#pragma unroll
        for (int mt = 0; mt < 2; mt++) {
            int r = R0 + mt*16 + lg;
            int grow = bbase + r;
            float2 kv0[8], kv1[8];
#pragma unroll
            for (int nt = 0; nt < 8; nt++) {
                int c = C0 + nt*8 + lt*2;
                kv0[nt] = *(const float2*)(g_k + (size_t)grow*CC + c);
                kv1[nt] = *(const float2*)(g_k + (size_t)(grow + 8)*CC + c);
            }
#pragma unroll
            for (int nt = 0; nt < 8; nt++) {
                int c = C0 + nt*8 + lt*2;
                uint32_t coff = ((uint32_t)(c >> 5))*8192u;
                int wloc = (c & 31) >> 1;
                uint32_t o0 = coff + swz(r, wloc), o1 = coff + swz(r + 8, wloc);
                float bv0 = __ldg(bva + c), bv1 = __ldg(bva + c + 1);
                float q0 = qs[c] * 16.0f, q1 = qs[c+1] * 16.0f;
                uint32_t uh0 = *(uint32_t*)(sm + OFF_ATH + o0);
                uint32_t uh1 = *(uint32_t*)(sm + OFF_ATH + o1);
                float a0 = exh(uh0, 0) * (acc[mt][nt][0] + bv0) * q0 * kv0[nt].x;
                float a1 = exh(uh0, 1) * (acc[mt][nt][1] + bv1) * q1 * kv0[nt].y;
                float a2 = exh(uh1, 0) * (acc[mt][nt][2] + bv0) * q0 * kv1[nt].x;
                float a3 = exh(uh1, 1) * (acc[mt][nt][3] + bv1) * q1 * kv1[nt].y;
                *(uint32_t*)(sm + OFF_ATH + o0) = pack2h(a0, a1);
                *(uint32_t*)(sm + OFF_ATH + o1) = pack2h(a2, a3);
            }
        }
    }

    // ======== Phase C: edge_out = (attn @ Woed)/256 + boed ========
    ZERO_ACC(acc);
    for (int ch = 0; ch < NCHK; ch++) {
        CP_WAIT0();
        __syncthreads();
        if (ch < 7) cpB(sbase + OFF_B + (((ch & 1) ^ 1))*BBUF_B, g_WoedT, (ch+1)*CHK, tid);
        mma_chunk1(sbase + OFF_ATH + ch*8192,
                   sbase + OFF_B + (ch & 1)*BBUF_B, acc, R0, C0, lane);
    }
    // epilogue C: scale back 1/256 and store
#pragma unroll
    for (int mt = 0; mt < 2; mt++) {
        int r = R0 + mt*16 + lg;
#pragma unroll
        for (int nt = 0; nt < 8; nt++) {
            int c = C0 + nt*8 + lt*2;
            float b0v = __ldg(boed + c), b1v = __ldg(boed + c + 1);
            *(float2*)(out_edge + ((size_t)bm*NN + r)*CC + c) =
                make_float2(acc[mt][nt][0]*0.00390625f + b0v,
                            acc[mt][nt][1]*0.00390625f + b1v);
            *(float2*)(out_edge + ((size_t)bm*NN + r + 8)*CC + c) =
                make_float2(acc[mt][nt][2]*0.00390625f + b0v,
                            acc[mt][nt][3]*0.00390625f + b1v);
        }
    }

    // ======== softmax (2-way split over n) + node projection ========
    {
        float* red  = (float*)(sm + OFF_A);
        float* red2 = (float*)(sm + OFF_A + 2048);
        float* nodes = (float*)(sm + OFF_NODES);

        const int c = tid & 255, half = tid >> 8;
        const int odd = c & 1;
        const int wloc = (c & 31) >> 1;
        const char* bh = sm + OFF_ATH + ((uint32_t)(c >> 5))*8192u;
        const int n0 = half*64;

        float mx = -1e30f;
#pragma unroll 8
        for (int i = 0; i < 64; i++) {
            float v = exh(*(const uint32_t*)(bh + swz(n0 + i, wloc)), odd);
            mx = fmaxf(mx, v);
        }
        red[tid] = mx;
        __syncthreads();
        mx = fmaxf(red[c], red[256 + c]);

        float s = 0.f, nv = 0.f;
        const float* vb = g_v + (size_t)((b << 7) + n0)*CC + c;
#pragma unroll 8
        for (int i = 0; i < 64; i++) {
            float v = exh(*(const uint32_t*)(bh + swz(n0 + i, wloc)), odd);
            float e = __expf((v - mx) * 0.00390625f);
            s += e;
            nv += e * vb[(size_t)i*CC];
        }
        __syncthreads();
        red[tid] = s; red2[tid] = nv;
        __syncthreads();
        if (tid < 256)
            nodes[c] = (red2[c] + red2[256 + c]) / (red[c] + red[256 + c]);
        __syncthreads();

        float a2 = 0.f;
        const int k0 = half*128;
#pragma unroll 8
        for (int k = 0; k < 128; k++)
            a2 += nodes[k0 + k] * Wond[(k0 + k)*CC + c];
        red[tid] = a2;
        __syncthreads();
        if (tid < 256)
            out_node[bm*CC + c] = red[c] + red[256 + c] + __ldg(bond + c);
    }
}

// ---------------- launch ----------------
extern "C" void kernel_launch(void* const* d_in, const int* in_sizes, int n_in,
                              void* d_out, int out_size)
{
    const float* mol_annot  = (const float*)d_in[0];
    const float* prot_annot = (const float*)d_in[1];
    const float* mol_adj    = (const float*)d_in[2];
    const float* prot_adj   = (const float*)d_in[3];
    const float* Wq   = (const float*)d_in[4];   const float* bq   = (const float*)d_in[5];
    const float* Wk   = (const float*)d_in[6];   const float* bk   = (const float*)d_in[7];
    const float* Wv   = (const float*)d_in[8];   const float* bv   = (const float*)d_in[9];
    const float* Wka  = (const float*)d_in[10];  const float* bka  = (const float*)d_in[11];
    const float* Wva  = (const float*)d_in[12];  const float* bva  = (const float*)d_in[13];
    const float* Wond = (const float*)d_in[14];  const float* bond = (const float*)d_in[15];
    const float* Woed = (const float*)d_in[16];  const float* boed = (const float*)d_in[17];

    float* out = (float*)d_out;
    const size_t ANNOT = (size_t)BB*NN*CC;
    const size_t ADJ   = (size_t)BB*NN*NN*CC;
    float* out_node       = out;
    float* out_prot_annot = out + ANNOT;
    float* out_edge       = out + 2*ANNOT;
    float* out_prot_adj   = out + 2*ANNOT + ADJ;

    cudaFuncSetAttribute(edge_kernel,
                         cudaFuncAttributeMaxDynamicSharedMemorySize, SMEM_BYTES);

    prep_kernel<<<312, 256>>>(Wka, Wva, Woed,
                              mol_annot, prot_annot, Wq, bq, Wk, bk, Wv, bv,
                              out_prot_annot);

    edge_kernel<<<ROWS_TOT, THREADS, SMEM_BYTES>>>(
        mol_adj, prot_adj, bka, bva, boed, bond, Wond,
        out_node, out_edge, out_prot_adj);
}

// round 17
// speedup vs baseline: 1.5869x; 1.1333x over previous
#include <cuda_runtime.h>
#include <cuda_fp16.h>
#include <stdint.h>
#include <math.h>

#define BB 8
#define NN 128
#define CC 256
#define ROWS_TOT (BB*NN)     /* 1024 */
#define CHK 32               /* K-chunk */
#define THREADS 512

// ---------------- scratch ----------------
__device__ float g_q[ROWS_TOT*CC];
__device__ float g_k[ROWS_TOT*CC];      // natural layout [bm][c]
__device__ float g_v[ROWS_TOT*CC];
__device__ __align__(16) __half g_WkaT[CC*CC];   // W^T, single fp16
__device__ __align__(16) __half g_WvaT[CC*CC];
__device__ __align__(16) __half g_WoedT[CC*CC];

// ---------------- helpers ----------------
__device__ __forceinline__ void mma_f16(float acc[4],
    uint32_t a0, uint32_t a1, uint32_t a2, uint32_t a3,
    uint32_t b0, uint32_t b1)
{
    asm volatile(
        "mma.sync.aligned.m16n8k16.row.col.f32.f16.f16.f32 "
        "{%0,%1,%2,%3}, {%4,%5,%6,%7}, {%8,%9}, {%0,%1,%2,%3};"
        : "+f"(acc[0]), "+f"(acc[1]), "+f"(acc[2]), "+f"(acc[3])
        : "r"(a0), "r"(a1), "r"(a2), "r"(a3), "r"(b0), "r"(b1));
}

#define LDSM_X4(rg, addr) \
    asm volatile("ldmatrix.sync.aligned.m8n8.x4.shared.b16 {%0,%1,%2,%3}, [%4];" \
        : "=r"((rg)[0]), "=r"((rg)[1]), "=r"((rg)[2]), "=r"((rg)[3]) : "r"(addr))

// two fp32 -> one packed fp16x2 word
__device__ __forceinline__ uint32_t pack2h(float a, float b) {
    return ((uint32_t)__half_as_ushort(__float2half_rn(b)) << 16)
         | __half_as_ushort(__float2half_rn(a));
}
__device__ __forceinline__ float exh(uint32_t u, int odd) {
    unsigned short s = odd ? (unsigned short)(u >> 16) : (unsigned short)(u & 0xffff);
    return __half2float(__ushort_as_half(s));
}

__device__ __forceinline__ uint32_t smem_to_u32(const void* p) {
    uint32_t a;
    asm("{ .reg .u64 t; cvta.to.shared.u64 t, %1; cvt.u32.u64 %0, t; }" : "=r"(a) : "l"(p));
    return a;
}

#define CP_ASYNC16(dst_u32, src_ptr) \
    asm volatile("cp.async.cg.shared.global [%0], [%1], 16;" \
        :: "r"(dst_u32), "l"(src_ptr) : "memory")
#define CP_COMMIT()  asm volatile("cp.async.commit_group;" ::: "memory")
#define CP_WAIT0()   asm volatile("cp.async.wait_group 0;" ::: "memory")

// Swizzle for 64-byte rows (32 fp16 = 16 words); 16B blocks stay contiguous.
__device__ __forceinline__ uint32_t swz(int row, int w) {
    return (uint32_t)(row*64 + ((w ^ (((row >> 1) & 3) << 2)) << 2));
}

// ---------------- SMEM layout (bytes) ----------------
#define OFF_QS    0          /* 1K */
#define OFF_NODES 1024       /* 1K */
#define OFF_A     2048       /* 4 bufs x 8K (single fp16 A) = 32K; reduce scratch later */
#define ABUF_B    8192
#define OFF_B     34816      /* 4 bufs x 16K (single fp16 weights) = 64K */
#define BBUF_B    16384
#define OFF_ATH   100352     /* attn (single fp16): 8 slabs x 8K = 64K */
#define SMEM_BYTES 165888

// ---------------- prep: weight transpose (fp16) + qkv + prot_annot copy -----
__global__ __launch_bounds__(256) void prep_kernel(
    const float* __restrict__ Wka, const float* __restrict__ Wva,
    const float* __restrict__ Woed,
    const float* __restrict__ mol, const float* __restrict__ prot,
    const float* __restrict__ Wq, const float* __restrict__ bq,
    const float* __restrict__ Wk, const float* __restrict__ bk,
    const float* __restrict__ Wv, const float* __restrict__ bv,
    float* __restrict__ out_prot_annot)
{
    __shared__ float SH[8448];
    int tid = threadIdx.x;
    int bid = blockIdx.x;
    if (bid < 24) {
        int mat = bid >> 3, k0 = (bid & 7) * CHK;
        const float* W = (mat == 0) ? Wka : (mat == 1) ? Wva : Woed;
        __half* G = (mat == 0) ? g_WkaT : (mat == 1) ? g_WvaT : g_WoedT;
        for (int i = tid; i < 32*256; i += 256) {
            int kk = i >> 8, n = i & 255;
            SH[kk*257 + n] = W[(k0 + kk)*CC + n];
        }
        __syncthreads();
        int n = tid;
        uint32_t w[16];
#pragma unroll
        for (int j = 0; j < 16; j++) {
            __half h0 = __float2half_rn(SH[(2*j)*257 + n]);
            __half h1 = __float2half_rn(SH[(2*j+1)*257 + n]);
            w[j] = ((uint32_t)__half_as_ushort(h1) << 16) | __half_as_ushort(h0);
        }
        uint4* d = (uint4*)(G + n*CC + k0);
#pragma unroll
        for (int j = 0; j < 4; j++)
            d[j] = make_uint4(w[j*4], w[j*4+1], w[j*4+2], w[j*4+3]);
    } else if (bid < 280) {
        // qkv: 4 rows per block, 256 blocks
        float* Am = SH;
        float* Ap = SH + 1056;
        int r0 = (bid - 24) * 4;
        for (int i = tid; i < 4*CC; i += 256) {
            int r = i >> 8, c = i & 255;
            Am[i] = mol [(r0 + r)*CC + c];
            Ap[i] = prot[(r0 + r)*CC + c];
        }
        __syncthreads();
        int c = tid;
        float aq[4], ak[4], av[4];
#pragma unroll
        for (int r = 0; r < 4; r++) { aq[r]=0.f; ak[r]=0.f; av[r]=0.f; }
        for (int k = 0; k < CC; k++) {
            float wq = Wq[k*CC + c], wk = Wk[k*CC + c], wv = Wv[k*CC + c];
#pragma unroll
            for (int r = 0; r < 4; r++) {
                float am = Am[r*CC + k], ap = Ap[r*CC + k];
                aq[r] += am*wq; ak[r] += ap*wk; av[r] += am*wv;
            }
        }
        float bqv = bq[c], bkv = bk[c], bvv = bv[c];
#pragma unroll
        for (int r = 0; r < 4; r++) {
            g_q[(r0+r)*CC + c] = aq[r] + bqv;
            g_k[(r0+r)*CC + c] = ak[r] + bkv;
            g_v[(r0+r)*CC + c] = av[r] + bvv;
        }
    } else {
        const float4* src = (const float4*)prot;
        float4* dst = (float4*)out_prot_annot;
        int base = (bid - 280) * 2048;
#pragma unroll
        for (int u = 0; u < 8; u++)
            dst[base + u*256 + tid] = src[base + u*256 + tid];
    }
}

extern __shared__ char smem_raw[];

// ---------------- staging (512 threads) ----------------
__device__ __forceinline__ void ldgA(float4 pf[2], const float* __restrict__ Ag,
                                     int k0, int tid)
{
#pragma unroll
    for (int u = 0; u < 2; u++) {
        int idx = u*THREADS + tid;
        int row = idx >> 3, j = idx & 7;
        pf[u] = *(const float4*)(Ag + row*CC + k0 + j*4);
    }
}

// single-fp16 A staging
__device__ __forceinline__ void stsA(char* ab, const float4 pf[2], int tid,
                                     float* __restrict__ outp, int k0)
{
#pragma unroll
    for (int u = 0; u < 2; u++) {
        int idx = u*THREADS + tid;
        int row = idx >> 3, j = idx & 7;
        uint32_t h01 = pack2h(pf[u].x, pf[u].y);
        uint32_t h23 = pack2h(pf[u].z, pf[u].w);
        *(uint2*)(ab + swz(row, j*2)) = make_uint2(h01, h23);
        if (outp) *(float4*)(outp + row*CC + k0 + j*4) = pf[u];
    }
}

// Weight chunk: single fp16, 16KB, 2 cp.async per thread, one commit group.
__device__ __forceinline__ void cpB(uint32_t bb,
    const __half* __restrict__ W, int k0, int tid)
{
#pragma unroll
    for (int u = 0; u < 2; u++) {
        int idx = u*THREADS + tid;
        int row = idx >> 2, t = idx & 3;
        CP_ASYNC16(bb + swz(row, t*4), W + row*CC + k0 + t*8);
    }
    CP_COMMIT();
}

// Single-term MMA over staged K=32 chunk (STRAIGHTLINE).
// A fp16 single, B fp16 single. Warp tile 32x64 at (R0, C0); acc[2][8][4].
__device__ __forceinline__ void mma_chunk1(
    uint32_t ah_b, uint32_t b_b,
    float acc[2][8][4], int R0, int C0, int lane)
{
    const int t = lane >> 3, r = lane & 7;
    const int arow = (t & 1)*8 + r, acolw = (t >> 1)*4;
    const int brow = (t >> 1)*8 + r, bcolw = (t & 1)*4;
#pragma unroll
    for (int kk = 0; kk < 2; kk++) {
        const int wA = kk*8;
        uint32_t a0[4], a1[4];
        LDSM_X4(a0, ah_b + swz(R0 + arow, wA + acolw));
        LDSM_X4(a1, ah_b + swz(R0 + 16 + arow, wA + acolw));
#pragma unroll
        for (int ntp = 0; ntp < 4; ntp++) {
            uint32_t bb[4];
            LDSM_X4(bb, b_b + swz(C0 + ntp*16 + brow, wA + bcolw));
            mma_f16(acc[0][2*ntp],   a0[0],a0[1],a0[2],a0[3], bb[0],bb[1]);
            mma_f16(acc[1][2*ntp],   a1[0],a1[1],a1[2],a1[3], bb[0],bb[1]);
            mma_f16(acc[0][2*ntp+1], a0[0],a0[1],a0[2],a0[3], bb[2],bb[3]);
            mma_f16(acc[1][2*ntp+1], a1[0],a1[1],a1[2],a1[3], bb[2],bb[3]);
        }
    }
}

#define ZERO_ACC(acc) \
    _Pragma("unroll") for (int mt = 0; mt < 2; mt++) \
    _Pragma("unroll") for (int nt = 0; nt < 8; nt++) \
    _Pragma("unroll") for (int i = 0; i < 4; i++) acc[mt][nt][i] = 0.f;

// ---------------- fused edge kernel, one CTA per (b,m), 512 threads ---------
// attn stored as SINGLE fp16, SCALED x256. 4-deep A/B rings, 1 barrier per
// 2 chunks (K order unchanged -> bitwise-identical numerics vs round 16).
__global__ __launch_bounds__(THREADS, 1) void edge_kernel(
    const float* __restrict__ mol_adj, const float* __restrict__ prot_adj,
    const float* __restrict__ bka,  const float* __restrict__ bva,
    const float* __restrict__ boed, const float* __restrict__ bond,
    const float* __restrict__ Wond,
    float* __restrict__ out_node, float* __restrict__ out_edge,
    float* __restrict__ out_prot_adj)
{
    char* sm = smem_raw;
    const uint32_t sbase = smem_to_u32(sm);
    const int tid = threadIdx.x, wid = tid >> 5, lane = tid & 31;
    const int lg = lane >> 2, lt = lane & 3;
    const int bm = blockIdx.x, b = bm >> 7;
    const int R0 = (wid >> 2)*32, C0 = (wid & 3)*64;   // 4x4 warp grid

    float* qs = (float*)(sm + OFF_QS);
    const float* Ap = prot_adj + (size_t)bm*NN*CC;
    const float* Am = mol_adj  + (size_t)bm*NN*CC;
    float* outp = out_prot_adj + (size_t)bm*NN*CC;

    if (tid < 256) qs[tid] = g_q[bm*CC + tid];

    float acc[2][8][4];
    float4 pfa[2], pfb[2];

    // prologue: prefetch pair 0
    ldgA(pfa, Ap, 0, tid);
    ldgA(pfb, Ap, CHK, tid);
    cpB(sbase + OFF_B + 0*BBUF_B, g_WkaT, 0, tid);
    cpB(sbase + OFF_B + 1*BBUF_B, g_WkaT, CHK, tid);
    __syncthreads();

    // ======== Phase A: prot_e (writes prot passthrough from pf) ========
    ZERO_ACC(acc);
    for (int p = 0; p < 4; p++) {
        const int ch0 = 2*p, ch1 = 2*p + 1;
        stsA(sm + OFF_A + (ch0 & 3)*ABUF_B, pfa, tid, outp, ch0*CHK);
        stsA(sm + OFF_A + (ch1 & 3)*ABUF_B, pfb, tid, outp, ch1*CHK);
        if (p < 3) { ldgA(pfa, Ap, (ch0+2)*CHK, tid); ldgA(pfb, Ap, (ch1+2)*CHK, tid); }
        else       { ldgA(pfa, Am, 0, tid);           ldgA(pfb, Am, CHK, tid); }
        CP_WAIT0();
        __syncthreads();
        if (p < 3) {
            cpB(sbase + OFF_B + ((ch0+2) & 3)*BBUF_B, g_WkaT, (ch0+2)*CHK, tid);
            cpB(sbase + OFF_B + ((ch1+2) & 3)*BBUF_B, g_WkaT, (ch1+2)*CHK, tid);
        } else {
            cpB(sbase + OFF_B + 0*BBUF_B, g_WvaT, 0, tid);
            cpB(sbase + OFF_B + 1*BBUF_B, g_WvaT, CHK, tid);
        }
        mma_chunk1(sbase + OFF_A + (ch0 & 3)*ABUF_B,
                   sbase + OFF_B + (ch0 & 3)*BBUF_B, acc, R0, C0, lane);
        mma_chunk1(sbase + OFF_A + (ch1 & 3)*ABUF_B,
                   sbase + OFF_B + (ch1 & 3)*BBUF_B, acc, R0, C0, lane);
    }
    // epilogue A: attn := fp16(pe + bka + 1)
#pragma unroll
    for (int mt = 0; mt < 2; mt++) {
        int r = R0 + mt*16 + lg;
#pragma unroll
        for (int nt = 0; nt < 8; nt++) {
            int c = C0 + nt*8 + lt*2;
            uint32_t coff = ((uint32_t)(c >> 5))*8192u;
            int wloc = (c & 31) >> 1;
            float b0v = __ldg(bka + c) + 1.0f, b1v = __ldg(bka + c + 1) + 1.0f;
            *(uint32_t*)(sm + OFF_ATH + coff + swz(r, wloc)) =
                pack2h(acc[mt][nt][0] + b0v, acc[mt][nt][1] + b1v);
            *(uint32_t*)(sm + OFF_ATH + coff + swz(r + 8, wloc)) =
                pack2h(acc[mt][nt][2] + b0v, acc[mt][nt][3] + b1v);
        }
    }

    // ======== Phase B: mol_e ========
    ZERO_ACC(acc);
    for (int p = 0; p < 4; p++) {
        const int ch0 = 2*p, ch1 = 2*p + 1;
        stsA(sm + OFF_A + (ch0 & 3)*ABUF_B, pfa, tid, (float*)0, 0);
        stsA(sm + OFF_A + (ch1 & 3)*ABUF_B, pfb, tid, (float*)0, 0);
        if (p < 3) { ldgA(pfa, Am, (ch0+2)*CHK, tid); ldgA(pfb, Am, (ch1+2)*CHK, tid); }
        CP_WAIT0();
        __syncthreads();
        if (p < 3) {
            cpB(sbase + OFF_B + ((ch0+2) & 3)*BBUF_B, g_WvaT, (ch0+2)*CHK, tid);
            cpB(sbase + OFF_B + ((ch1+2) & 3)*BBUF_B, g_WvaT, (ch1+2)*CHK, tid);
        } else {
            cpB(sbase + OFF_B + 0*BBUF_B, g_WoedT, 0, tid);
            cpB(sbase + OFF_B + 1*BBUF_B, g_WoedT, CHK, tid);
        }
        mma_chunk1(sbase + OFF_A + (ch0 & 3)*ABUF_B,
                   sbase + OFF_B + (ch0 & 3)*BBUF_B, acc, R0, C0, lane);
        mma_chunk1(sbase + OFF_A + (ch1 & 3)*ABUF_B,
                   sbase + OFF_B + (ch1 & 3)*BBUF_B, acc, R0, C0, lane);
    }
    // epilogue B: attn_scaled = pe * (me + bva) * (q*16) * k   [= true*256]
    // g_k loads hoisted per mt-group into registers (MLP 2 -> 16)
    {
        const int bbase = b << 7;
#pragma unroll
        for (int mt = 0; mt < 2; mt++) {
            int r = R0 + mt*16 + lg;
            int grow = bbase + r;
            float2 kv0[8], kv1[8];
#pragma unroll
            for (int nt = 0; nt < 8; nt++) {
                int c = C0 + nt*8 + lt*2;
                kv0[nt] = *(const float2*)(g_k + (size_t)grow*CC + c);
                kv1[nt] = *(const float2*)(g_k + (size_t)(grow + 8)*CC + c);
            }
#pragma unroll
            for (int nt = 0; nt < 8; nt++) {
                int c = C0 + nt*8 + lt*2;
                uint32_t coff = ((uint32_t)(c >> 5))*8192u;
                int wloc = (c & 31) >> 1;
                uint32_t o0 = coff + swz(r, wloc), o1 = coff + swz(r + 8, wloc);
                float bv0 = __ldg(bva + c), bv1 = __ldg(bva + c + 1);
                float q0 = qs[c] * 16.0f, q1 = qs[c+1] * 16.0f;
                uint32_t uh0 = *(uint32_t*)(sm + OFF_ATH + o0);
                uint32_t uh1 = *(uint32_t*)(sm + OFF_ATH + o1);
                float a0 = exh(uh0, 0) * (acc[mt][nt][0] + bv0) * q0 * kv0[nt].x;
                float a1 = exh(uh0, 1) * (acc[mt][nt][1] + bv1) * q1 * kv0[nt].y;
                float a2 = exh(uh1, 0) * (acc[mt][nt][2] + bv0) * q0 * kv1[nt].x;
                float a3 = exh(uh1, 1) * (acc[mt][nt][3] + bv1) * q1 * kv1[nt].y;
                *(uint32_t*)(sm + OFF_ATH + o0) = pack2h(a0, a1);
                *(uint32_t*)(sm + OFF_ATH + o1) = pack2h(a2, a3);
            }
        }
    }

    // ======== Phase C: edge_out = (attn @ Woed)/256 + boed ========
    ZERO_ACC(acc);
    for (int p = 0; p < 4; p++) {
        const int ch0 = 2*p, ch1 = 2*p + 1;
        CP_WAIT0();
        __syncthreads();
        if (p < 3) {
            cpB(sbase + OFF_B + ((ch0+2) & 3)*BBUF_B, g_WoedT, (ch0+2)*CHK, tid);
            cpB(sbase + OFF_B + ((ch1+2) & 3)*BBUF_B, g_WoedT, (ch1+2)*CHK, tid);
        }
        mma_chunk1(sbase + OFF_ATH + ch0*8192,
                   sbase + OFF_B + (ch0 & 3)*BBUF_B, acc, R0, C0, lane);
        mma_chunk1(sbase + OFF_ATH + ch1*8192,
                   sbase + OFF_B + (ch1 & 3)*BBUF_B, acc, R0, C0, lane);
    }
    // epilogue C: scale back 1/256 and store
#pragma unroll
    for (int mt = 0; mt < 2; mt++) {
        int r = R0 + mt*16 + lg;
#pragma unroll
        for (int nt = 0; nt < 8; nt++) {
            int c = C0 + nt*8 + lt*2;
            float b0v = __ldg(boed + c), b1v = __ldg(boed + c + 1);
            *(float2*)(out_edge + ((size_t)bm*NN + r)*CC + c) =
                make_float2(acc[mt][nt][0]*0.00390625f + b0v,
                            acc[mt][nt][1]*0.00390625f + b1v);
            *(float2*)(out_edge + ((size_t)bm*NN + r + 8)*CC + c) =
                make_float2(acc[mt][nt][2]*0.00390625f + b0v,
                            acc[mt][nt][3]*0.00390625f + b1v);
        }
    }

    // ======== softmax (2-way split over n) + node projection ========
    {
        float* red  = (float*)(sm + OFF_A);
        float* red2 = (float*)(sm + OFF_A + 2048);
        float* nodes = (float*)(sm + OFF_NODES);

        const int c = tid & 255, half = tid >> 8;
        const int odd = c & 1;
        const int wloc = (c & 31) >> 1;
        const char* bh = sm + OFF_ATH + ((uint32_t)(c >> 5))*8192u;
        const int n0 = half*64;

        float mx = -1e30f;
#pragma unroll 8
        for (int i = 0; i < 64; i++) {
            float v = exh(*(const uint32_t*)(bh + swz(n0 + i, wloc)), odd);
            mx = fmaxf(mx, v);
        }
        red[tid] = mx;
        __syncthreads();
        mx = fmaxf(red[c], red[256 + c]);

        float s = 0.f, nv = 0.f;
        const float* vb = g_v + (size_t)((b << 7) + n0)*CC + c;
#pragma unroll 8
        for (int i = 0; i < 64; i++) {
            float v = exh(*(const uint32_t*)(bh + swz(n0 + i, wloc)), odd);
            float e = __expf((v - mx) * 0.00390625f);
            s += e;
            nv += e * vb[(size_t)i*CC];
        }
        __syncthreads();
        red[tid] = s; red2[tid] = nv;
        __syncthreads();
        if (tid < 256)
            nodes[c] = (red2[c] + red2[256 + c]) / (red[c] + red[256 + c]);
        __syncthreads();

        float a2 = 0.f;
        const int k0 = half*128;
#pragma unroll 8
        for (int k = 0; k < 128; k++)
            a2 += nodes[k0 + k] * Wond[(k0 + k)*CC + c];
        red[tid] = a2;
        __syncthreads();
        if (tid < 256)
            out_node[bm*CC + c] = red[c] + red[256 + c] + __ldg(bond + c);
    }
}

// ---------------- launch ----------------
extern "C" void kernel_launch(void* const* d_in, const int* in_sizes, int n_in,
                              void* d_out, int out_size)
{
    const float* mol_annot  = (const float*)d_in[0];
    const float* prot_annot = (const float*)d_in[1];
    const float* mol_adj    = (const float*)d_in[2];
    const float* prot_adj   = (const float*)d_in[3];
    const float* Wq   = (const float*)d_in[4];   const float* bq   = (const float*)d_in[5];
    const float* Wk   = (const float*)d_in[6];   const float* bk   = (const float*)d_in[7];
    const float* Wv   = (const float*)d_in[8];   const float* bv   = (const float*)d_in[9];
    const float* Wka  = (const float*)d_in[10];  const float* bka  = (const float*)d_in[11];
    const float* Wva  = (const float*)d_in[12];  const float* bva  = (const float*)d_in[13];
    const float* Wond = (const float*)d_in[14];  const float* bond = (const float*)d_in[15];
    const float* Woed = (const float*)d_in[16];  const float* boed = (const float*)d_in[17];

    float* out = (float*)d_out;
    const size_t ANNOT = (size_t)BB*NN*CC;
    const size_t ADJ   = (size_t)BB*NN*NN*CC;
    float* out_node       = out;
    float* out_prot_annot = out + ANNOT;
    float* out_edge       = out + 2*ANNOT;
    float* out_prot_adj   = out + 2*ANNOT + ADJ;

    cudaFuncSetAttribute(edge_kernel,
                         cudaFuncAttributeMaxDynamicSharedMemorySize, SMEM_BYTES);

    prep_kernel<<<312, 256>>>(Wka, Wva, Woed,
                              mol_annot, prot_annot, Wq, bq, Wk, bk, Wv, bv,
                              out_prot_annot);

    edge_kernel<<<ROWS_TOT, THREADS, SMEM_BYTES>>>(
        mol_adj, prot_adj, bka, bva, boed, bond, Wond,
        out_node, out_edge, out_prot_adj);
}